// round 1
// baseline (speedup 1.0000x reference)
#include <cuda_runtime.h>
#include <cuda_bf16.h>
#include <math.h>

// Problem constants
#define NIMG 8
#define H 768
#define W 1024
#define HW (H*W)              // 786432
#define S 30000
#define WORDS (HW/32)         // 24576
#define NTOT (NIMG*HW)        // 6291456
#define GRIDX ((S+255)/256)   // 118
#define MASKV (-1e-8f)

// Scratch (device globals -- no allocation allowed)
__device__ unsigned g_bits[NIMG*WORDS];    // edge-mask bitmask, 32 px/word
__device__ int      g_prefix[NIMG*WORDS];  // inclusive popcount prefix per image
__device__ int      g_emax_bits[NIMG];     // per-image max edge (float bits, positive)
__device__ int      g_count[NIMG];         // total edge pixels per image
__device__ float    g_part[NIMG*GRIDX*4];  // per-block partial sums: eq, un, n_eq, n_un

// ---------------------------------------------------------------------------
// Sobel at interior pixel (r,c), channel-0 plane g (row stride W).
// Fixed row-major accumulation; *_rn intrinsics prevent fma contraction so the
// rounding sequence is reproducible. Weights +-1,+-2 are exact multipliers.
// ---------------------------------------------------------------------------
__device__ __forceinline__ void sobel_at(const float* __restrict__ g, int r, int c,
                                         float& gx, float& gy) {
    const float* r0 = g + (r-1)*W + c;
    const float* r1 = g + r*W + c;
    const float* r2 = g + (r+1)*W + c;
    float a00 = r0[-1], a01 = r0[0], a02 = r0[1];
    float a10 = r1[-1],               a12 = r1[1];
    float a20 = r2[-1], a21 = r2[0], a22 = r2[1];
    // gx kernel: [[-1,0,1],[-2,0,2],[-1,0,1]] (cross-correlation, no flip)
    float x = __fmul_rn(-1.0f, a00);
    x = __fadd_rn(x, a02);
    x = __fadd_rn(x, __fmul_rn(-2.0f, a10));
    x = __fadd_rn(x, __fmul_rn( 2.0f, a12));
    x = __fadd_rn(x, __fmul_rn(-1.0f, a20));
    x = __fadd_rn(x, a22);
    gx = x;
    // gy kernel: [[1,2,1],[0,0,0],[-1,-2,-1]]
    float y = a00;
    y = __fadd_rn(y, __fmul_rn( 2.0f, a01));
    y = __fadd_rn(y, a02);
    y = __fadd_rn(y, __fmul_rn(-1.0f, a20));
    y = __fadd_rn(y, __fmul_rn(-2.0f, a21));
    y = __fadd_rn(y, __fmul_rn(-1.0f, a22));
    gy = y;
}

__device__ __forceinline__ float edge_mag(float gx, float gy) {
    float e2 = __fadd_rn(__fadd_rn(__fmul_rn(gx, gx), __fmul_rn(gy, gy)), 1e-6f);
    return sqrtf(e2);
}

// ---------------------------------------------------------------------------
__global__ void k_init() {
    if (threadIdx.x < NIMG) g_emax_bits[threadIdx.x] = 0;
}

// Pass 1: Sobel magnitude + per-image max (block tree + int atomicMax on bits).
__global__ void k_sobel_max(const float* __restrict__ images) {
    int idx = blockIdx.x * 256 + threadIdx.x;   // grid exactly covers NTOT
    int img = idx / HW;
    int p   = idx - img * HW;
    int r = p / W, c = p - r * W;
    float e = 0.0f;
    if (r > 0 && r < H-1 && c > 0 && c < W-1) {
        float gx, gy;
        sobel_at(images + (size_t)img * 3 * HW, r, c, gx, gy);
        e = edge_mag(gx, gy);
    }
    __shared__ float sm[256];
    sm[threadIdx.x] = e;
    __syncthreads();
    #pragma unroll
    for (int o = 128; o > 0; o >>= 1) {
        if (threadIdx.x < o) sm[threadIdx.x] = fmaxf(sm[threadIdx.x], sm[threadIdx.x + o]);
        __syncthreads();
    }
    if (threadIdx.x == 0) {
        // HW % 256 == 0 -> block lives in one image; values > 0 so int-bit max valid
        atomicMax(&g_emax_bits[img], __float_as_int(sm[0]));
    }
}

// Pass 2: recompute Sobel, threshold against emax*0.1, ballot into bitmask.
__global__ void k_bits(const float* __restrict__ images) {
    int idx = blockIdx.x * 256 + threadIdx.x;
    int img = idx / HW;
    int p   = idx - img * HW;
    int r = p / W, c = p - r * W;
    float e = 0.0f;
    if (r > 0 && r < H-1 && c > 0 && c < W-1) {
        float gx, gy;
        sobel_at(images + (size_t)img * 3 * HW, r, c, gx, gy);
        e = edge_mag(gx, gy);
    }
    float thr = __fmul_rn(__int_as_float(g_emax_bits[img]), 0.1f);
    unsigned bal = __ballot_sync(0xFFFFFFFFu, e >= thr);   // border e=0 < thr -> false
    if ((threadIdx.x & 31) == 0) g_bits[idx >> 5] = bal;
}

// Pass 3: inclusive prefix popcount over each image's 24576 words. 1 block/image.
__global__ void k_scan() {
    int img = blockIdx.x;
    int tid = threadIdx.x;
    const unsigned* bits = g_bits + img * WORDS;
    int* P = g_prefix + img * WORDS;
    __shared__ int sh[1024];
    __shared__ int carry_s;
    if (tid == 0) carry_s = 0;
    __syncthreads();
    #pragma unroll 1
    for (int chunk = 0; chunk < WORDS/1024; chunk++) {
        int base = chunk * 1024;
        int v = __popc(bits[base + tid]);
        sh[tid] = v;
        __syncthreads();
        #pragma unroll
        for (int off = 1; off < 1024; off <<= 1) {
            int t = (tid >= off) ? sh[tid - off] : 0;
            __syncthreads();
            sh[tid] += t;
            __syncthreads();
        }
        int inc = sh[tid] + carry_s;
        P[base + tid] = inc;
        __syncthreads();
        if (tid == 1023) carry_s = inc;
        __syncthreads();
    }
    if (tid == 0) g_count[img] = carry_s;
}

// Pass 4: per-anchor sampling + ranking loss; deterministic block reduction.
__global__ void k_anchor(const float* __restrict__ inp,
                         const float* __restrict__ tgt,
                         const float* __restrict__ images,
                         const int* __restrict__ anchor_rand,
                         const int* __restrict__ dist_rand) {
    const int img = blockIdx.y;
    const int s   = blockIdx.x * 256 + threadIdx.x;

    float eq = 0.0f, un = 0.0f, ne = 0.0f, nu = 0.0f;

    if (s < S) {
        const float UP = logf(1.03f);
        const float LO = logf(0.9708737864077669f);   // f32(1.0/1.03 computed in double)

        int cnt = g_count[img];                        // >= 1 always (argmax pixel passes)
        int k   = anchor_rand[img * S + s] % cnt;

        // binary search: smallest w with prefix[w] > k
        const int* P = g_prefix + img * WORDS;
        int lo = 0, hi = WORDS;
        while (lo < hi) {
            int mid = (lo + hi) >> 1;
            if (P[mid] > k) hi = mid; else lo = mid + 1;
        }
        int prev = lo ? P[lo - 1] : 0;
        int j = k - prev;
        unsigned wbits = g_bits[img * WORDS + lo];
        for (int t = 0; t < j; t++) wbits &= wbits - 1;   // drop j lowest set bits
        int sel = lo * 32 + (__ffs(wbits) - 1);

        int ra = sel / W, ca = sel - ra * W;              // interior (border never selected)
        float gx, gy;
        sobel_at(images + (size_t)img * 3 * HW, ra, ca, gx, gy);
        float th = atan2f(gy, gx);
        float ct = cosf(th), st = sinf(th);

        int lin[4];
        #pragma unroll
        for (int jj = 0; jj < 4; jj++) {
            float d = (float)dist_rand[(img * 4 + jj) * S + s] + 2.0f;
            if (jj < 2) d = -d;                           // sign = [-1,-1,1,1]
            int cc = ca + (int)rintf(__fmul_rn(d, ct));   // jnp.round = half-to-even
            int rr = ra + (int)rintf(__fmul_rn(d, st));
            cc = min(max(cc, 0), W - 1);
            rr = min(max(rr, 0), H - 1);
            lin[jj] = rr * W + cc;
        }

        const float* ip = inp + (size_t)img * HW;
        const float* tp = tgt + (size_t)img * HW;
        #pragma unroll
        for (int p = 0; p < 3; p++) {
            int a = lin[p], b = lin[p + 1];
            float iA = ip[a], iB = ip[b];
            float trA = tp[a], trB = tp[b];
            float cm = (trA > MASKV && trB > MASKV) ? 1.0f : 0.0f;
            float lr = __fadd_rn(logf(fmaxf(trA, 1e-8f)), -logf(fmaxf(trB, 1e-8f)));
            float diff = iA - iB;
            bool meq = (lr < UP) && (lr > LO);
            if (meq) {
                float ad = fabsf(diff);
                float sl1 = (ad < 1.0f) ? 0.5f * diff * diff : ad - 0.5f;
                eq += sl1 * cm;
                ne += cm;
            } else {
                float lab = (lr >= UP) ? 1.0f : -1.0f;
                float x = -diff * lab;
                float sp = fmaxf(x, 0.0f) + log1pf(expf(-fabsf(x)));  // logaddexp(x,0)
                un += sp * cm;
                nu += cm;
            }
        }
    }

    // deterministic block tree reduction of the 4 accumulators
    __shared__ float s0[256], s1[256], s2[256], s3[256];
    int t = threadIdx.x;
    s0[t] = eq; s1[t] = un; s2[t] = ne; s3[t] = nu;
    __syncthreads();
    #pragma unroll
    for (int o = 128; o > 0; o >>= 1) {
        if (t < o) {
            s0[t] += s0[t + o]; s1[t] += s1[t + o];
            s2[t] += s2[t + o]; s3[t] += s3[t + o];
        }
        __syncthreads();
    }
    if (t == 0) {
        int base = (img * GRIDX + blockIdx.x) * 4;
        g_part[base + 0] = s0[0];
        g_part[base + 1] = s1[0];
        g_part[base + 2] = s2[0];
        g_part[base + 3] = s3[0];
    }
}

// Pass 5: final reduction. 1 warp per image (fixed-order strided + shuffle tree).
__global__ void k_final(float* __restrict__ out) {
    int tid = threadIdx.x;          // 256 threads = 8 warps
    int img = tid >> 5, lane = tid & 31;
    float v0 = 0, v1 = 0, v2 = 0, v3 = 0;
    for (int b = lane; b < GRIDX; b += 32) {
        int base = (img * GRIDX + b) * 4;
        v0 += g_part[base + 0];
        v1 += g_part[base + 1];
        v2 += g_part[base + 2];
        v3 += g_part[base + 3];
    }
    #pragma unroll
    for (int o = 16; o > 0; o >>= 1) {
        v0 += __shfl_down_sync(0xFFFFFFFFu, v0, o);
        v1 += __shfl_down_sync(0xFFFFFFFFu, v1, o);
        v2 += __shfl_down_sync(0xFFFFFFFFu, v2, o);
        v3 += __shfl_down_sync(0xFFFFFFFFu, v3, o);
    }
    __shared__ float li[NIMG];
    if (lane == 0)
        li[img] = v0 / fmaxf(v2, 1.0f) + v1 / fmaxf(v3, 1.0f);   // ALPHA = 1
    __syncthreads();
    if (tid == 0) {
        float sum = 0.0f;
        for (int i = 0; i < NIMG; i++) sum += li[i];
        out[0] = sum / (float)NIMG;
    }
}

// ---------------------------------------------------------------------------
extern "C" void kernel_launch(void* const* d_in, const int* in_sizes, int n_in,
                              void* d_out, int out_size) {
    const float* inp    = (const float*)d_in[0];
    const float* tgt    = (const float*)d_in[1];
    const float* images = (const float*)d_in[2];
    const int*   anc    = (const int*)d_in[3];
    const int*   dst    = (const int*)d_in[4];
    float* out = (float*)d_out;

    k_init<<<1, 32>>>();
    k_sobel_max<<<NTOT / 256, 256>>>(images);
    k_bits<<<NTOT / 256, 256>>>(images);
    k_scan<<<NIMG, 1024>>>();
    k_anchor<<<dim3(GRIDX, NIMG), 256>>>(inp, tgt, images, anc, dst);
    k_final<<<1, 256>>>(out);
}

// round 2
// speedup vs baseline: 1.8614x; 1.8614x over previous
#include <cuda_runtime.h>
#include <cuda_bf16.h>
#include <math.h>

// Problem constants
#define NIMG 8
#define H 768
#define W 1024
#define HW (H*W)              // 786432
#define S 30000
#define WORDS (HW/32)         // 24576
#define NBLK 24               // scan blocks per image (WORDS/1024)
#define GRIDX ((S+255)/256)   // 118
#define MASKV (-1e-8f)

// Scratch (device globals -- no allocation allowed)
__device__ unsigned g_bits[NIMG*WORDS];    // edge-mask bitmask, 32 px/word
__device__ int      g_prefix[NIMG*WORDS];  // LOCAL inclusive popcount prefix (per 1024-word block)
__device__ int      g_bsum[NIMG*NBLK];     // per-block popcount totals
__device__ int      g_boff[NIMG*NBLK];     // exclusive offsets of blocks within image
__device__ int      g_emax_bits[NIMG];     // per-image max edge (float bits, positive)
__device__ int      g_count[NIMG];         // total edge pixels per image
__device__ float    g_part[NIMG*GRIDX*4];  // per-block partials: eq, un, n_eq, n_un

// ---------------------------------------------------------------------------
// Sobel arithmetic: EXACT rounding sequence (no fma contraction), row-major.
// ---------------------------------------------------------------------------
__device__ __forceinline__ void sobel_gxgy(float a00, float a01, float a02,
                                           float a10, float a12,
                                           float a20, float a21, float a22,
                                           float& gx, float& gy) {
    float x = __fmul_rn(-1.0f, a00);
    x = __fadd_rn(x, a02);
    x = __fadd_rn(x, __fmul_rn(-2.0f, a10));
    x = __fadd_rn(x, __fmul_rn( 2.0f, a12));
    x = __fadd_rn(x, __fmul_rn(-1.0f, a20));
    x = __fadd_rn(x, a22);
    gx = x;
    float y = a00;
    y = __fadd_rn(y, __fmul_rn( 2.0f, a01));
    y = __fadd_rn(y, a02);
    y = __fadd_rn(y, __fmul_rn(-1.0f, a20));
    y = __fadd_rn(y, __fmul_rn(-2.0f, a21));
    y = __fadd_rn(y, __fmul_rn(-1.0f, a22));
    gy = y;
}

__device__ __forceinline__ float edge_mag(float gx, float gy) {
    float e2 = __fadd_rn(__fadd_rn(__fmul_rn(gx, gx), __fmul_rn(gy, gy)), 1e-6f);
    return sqrtf(e2);
}

// Load a 3-row x 6-col window for 4 pixels starting at column c0=4*tid.
// win[k][0]=col c0-1 ... win[k][5]=col c0+4. Missing edge cols read as 0
// (only consumed by border pixels whose e is forced to 0).
__device__ __forceinline__ void load_win(const float* __restrict__ g, int r, int tid,
                                         float win[3][6]) {
    int c0 = tid * 4;
    #pragma unroll
    for (int k = 0; k < 3; k++) {
        const float* row = g + (r - 1 + k) * W;
        float4 m = *(const float4*)(row + c0);
        win[k][1] = m.x; win[k][2] = m.y; win[k][3] = m.z; win[k][4] = m.w;
        win[k][0] = (tid > 0)   ? row[c0 - 1] : 0.0f;
        win[k][5] = (tid < 255) ? row[c0 + 4] : 0.0f;
    }
}

// ---------------------------------------------------------------------------
__global__ void k_init() {
    if (threadIdx.x < NIMG) g_emax_bits[threadIdx.x] = 0;
}

// Pass 1: per-row Sobel max. One block = one interior row (4 px / thread).
__global__ void k_sobel_max(const float* __restrict__ images) {
    const int r   = blockIdx.x + 1;          // 1..H-2
    const int img = blockIdx.y;
    const int tid = threadIdx.x;
    const float* g = images + (size_t)img * 3 * HW;

    float win[3][6];
    load_win(g, r, tid, win);

    float em = 0.0f;
    #pragma unroll
    for (int i = 0; i < 4; i++) {
        float gx, gy;
        sobel_gxgy(win[0][i], win[0][i+1], win[0][i+2],
                   win[1][i],             win[1][i+2],
                   win[2][i], win[2][i+1], win[2][i+2], gx, gy);
        float e = edge_mag(gx, gy);
        if ((tid == 0 && i == 0) || (tid == 255 && i == 3)) e = 0.0f;  // border cols
        em = fmaxf(em, e);
    }

    __shared__ float sm[256];
    sm[tid] = em;
    __syncthreads();
    #pragma unroll
    for (int o = 128; o > 0; o >>= 1) {
        if (tid < o) sm[tid] = fmaxf(sm[tid], sm[tid + o]);
        __syncthreads();
    }
    if (tid == 0) atomicMax(&g_emax_bits[img], __float_as_int(sm[0]));
}

// Pass 2: per-row threshold -> bitmask. One block = one row (incl. border rows).
__global__ void k_bits(const float* __restrict__ images) {
    const int r   = blockIdx.x;              // 0..H-1
    const int img = blockIdx.y;
    const int tid = threadIdx.x;

    unsigned nib = 0;
    if (r > 0 && r < H - 1) {
        const float* g = images + (size_t)img * 3 * HW;
        float win[3][6];
        load_win(g, r, tid, win);
        const float thr = __fmul_rn(__int_as_float(g_emax_bits[img]), 0.1f);
        #pragma unroll
        for (int i = 0; i < 4; i++) {
            float gx, gy;
            sobel_gxgy(win[0][i], win[0][i+1], win[0][i+2],
                       win[1][i],             win[1][i+2],
                       win[2][i], win[2][i+1], win[2][i+2], gx, gy);
            bool on = edge_mag(gx, gy) >= thr;
            if ((tid == 0 && i == 0) || (tid == 255 && i == 3)) on = false;
            nib |= (unsigned)on << i;
        }
    }

    __shared__ unsigned char nib_s[256];
    nib_s[tid] = (unsigned char)nib;
    __syncthreads();
    if (tid < 32) {
        unsigned w = 0;
        #pragma unroll
        for (int i = 0; i < 8; i++) w |= (unsigned)nib_s[tid * 8 + i] << (4 * i);
        g_bits[img * WORDS + r * 32 + tid] = w;
    }
}

// Pass 3a: local inclusive prefix within each 1024-word block (warp-shuffle scan).
__global__ void k_scan_local() {
    const int img = blockIdx.y, blk = blockIdx.x;
    const int tid = threadIdx.x, lane = tid & 31, wid = tid >> 5;
    const int gi  = img * WORDS + blk * 1024 + tid;

    int v = __popc(g_bits[gi]);
    #pragma unroll
    for (int o = 1; o < 32; o <<= 1) {
        int t = __shfl_up_sync(0xFFFFFFFFu, v, o);
        if (lane >= o) v += t;
    }
    __shared__ int wsum[32];
    if (lane == 31) wsum[wid] = v;
    __syncthreads();
    if (tid < 32) {
        int x = wsum[tid];
        #pragma unroll
        for (int o = 1; o < 32; o <<= 1) {
            int t = __shfl_up_sync(0xFFFFFFFFu, x, o);
            if (tid >= o) x += t;
        }
        wsum[tid] = x;
    }
    __syncthreads();
    int incl = v + (wid ? wsum[wid - 1] : 0);
    g_prefix[gi] = incl;                              // LOCAL inclusive
    if (tid == 1023) g_bsum[img * NBLK + blk] = incl; // block total
}

// Pass 3b: scan the 24 block totals per image (1 warp/image, 1 block total).
__global__ void k_scan_offsets() {
    const int tid = threadIdx.x, img = tid >> 5, lane = tid & 31;
    int v = (lane < NBLK) ? g_bsum[img * NBLK + lane] : 0;
    int own = v;
    #pragma unroll
    for (int o = 1; o < 32; o <<= 1) {
        int t = __shfl_up_sync(0xFFFFFFFFu, v, o);
        if (lane >= o) v += t;
    }
    if (lane < NBLK) g_boff[img * NBLK + lane] = v - own;  // exclusive offset
    if (lane == NBLK - 1) g_count[img] = v;
}

// Pass 4: per-anchor sampling + ranking loss; two-level rank lookup.
__global__ void k_anchor(const float* __restrict__ inp,
                         const float* __restrict__ tgt,
                         const float* __restrict__ images,
                         const int* __restrict__ anchor_rand,
                         const int* __restrict__ dist_rand) {
    const int img = blockIdx.y;
    const int s   = blockIdx.x * 256 + threadIdx.x;

    __shared__ int boff_s[NBLK];
    __shared__ int cnt_s;
    if (threadIdx.x < NBLK) boff_s[threadIdx.x] = g_boff[img * NBLK + threadIdx.x];
    if (threadIdx.x == 0)   cnt_s = g_count[img];
    __syncthreads();

    float eq = 0.0f, un = 0.0f, ne = 0.0f, nu = 0.0f;

    if (s < S) {
        const float UP = logf(1.03f);
        const float LO = logf(0.9708737864077669f);   // f32(1.0/1.03 in double)

        int k = anchor_rand[img * S + s] % cnt_s;

        // level 1: which 1024-word block (largest b with boff<=k)
        int b = 0;
        #pragma unroll
        for (int i = 1; i < NBLK; i++) if (boff_s[i] <= k) b = i;
        int k2 = k - boff_s[b];

        // level 2: binary search local inclusive prefix (smallest w with P>k2)
        const int base = img * WORDS + b * 1024;
        int lo = 0, hi = 1024;
        while (lo < hi) {
            int mid = (lo + hi) >> 1;
            if (g_prefix[base + mid] > k2) hi = mid; else lo = mid + 1;
        }
        int prev = lo ? g_prefix[base + lo - 1] : 0;
        int j = k2 - prev;
        unsigned wbits = g_bits[base + lo];
        for (int t = 0; t < j; t++) wbits &= wbits - 1;   // drop j lowest set bits
        int sel = (b * 1024 + lo) * 32 + (__ffs(wbits) - 1);

        int ra = sel >> 10, ca = sel & 1023;              // W = 1024
        const float* g = images + (size_t)img * 3 * HW;
        const float* r0 = g + (ra - 1) * W + ca;
        const float* r1 = g + ra * W + ca;
        const float* r2 = g + (ra + 1) * W + ca;
        float gx, gy;
        sobel_gxgy(r0[-1], r0[0], r0[1], r1[-1], r1[1], r2[-1], r2[0], r2[1], gx, gy);
        float th = atan2f(gy, gx);
        float ct = cosf(th), st = sinf(th);

        int lin[4];
        #pragma unroll
        for (int jj = 0; jj < 4; jj++) {
            float d = (float)dist_rand[(img * 4 + jj) * S + s] + 2.0f;
            if (jj < 2) d = -d;                           // sign = [-1,-1,1,1]
            int cc = ca + (int)rintf(__fmul_rn(d, ct));   // half-to-even round
            int rr = ra + (int)rintf(__fmul_rn(d, st));
            cc = min(max(cc, 0), W - 1);
            rr = min(max(rr, 0), H - 1);
            lin[jj] = rr * W + cc;
        }

        const float* ip = inp + (size_t)img * HW;
        const float* tp = tgt + (size_t)img * HW;
        #pragma unroll
        for (int p = 0; p < 3; p++) {
            int a = lin[p], bq = lin[p + 1];
            float iA = ip[a], iB = ip[bq];
            float trA = tp[a], trB = tp[bq];
            float cm = (trA > MASKV && trB > MASKV) ? 1.0f : 0.0f;
            float lr = __fadd_rn(logf(fmaxf(trA, 1e-8f)), -logf(fmaxf(trB, 1e-8f)));
            float diff = iA - iB;
            bool meq = (lr < UP) && (lr > LO);
            if (meq) {
                float ad = fabsf(diff);
                float sl1 = (ad < 1.0f) ? 0.5f * diff * diff : ad - 0.5f;
                eq += sl1 * cm;
                ne += cm;
            } else {
                float lab = (lr >= UP) ? 1.0f : -1.0f;
                float x = -diff * lab;
                float sp = fmaxf(x, 0.0f) + log1pf(expf(-fabsf(x)));  // softplus
                un += sp * cm;
                nu += cm;
            }
        }
    }

    __shared__ float s0[256], s1[256], s2[256], s3[256];
    int t = threadIdx.x;
    s0[t] = eq; s1[t] = un; s2[t] = ne; s3[t] = nu;
    __syncthreads();
    #pragma unroll
    for (int o = 128; o > 0; o >>= 1) {
        if (t < o) {
            s0[t] += s0[t + o]; s1[t] += s1[t + o];
            s2[t] += s2[t + o]; s3[t] += s3[t + o];
        }
        __syncthreads();
    }
    if (t == 0) {
        int base = (img * GRIDX + blockIdx.x) * 4;
        g_part[base + 0] = s0[0];
        g_part[base + 1] = s1[0];
        g_part[base + 2] = s2[0];
        g_part[base + 3] = s3[0];
    }
}

// Pass 5: final reduction. 1 warp per image (fixed-order strided + shuffle tree).
__global__ void k_final(float* __restrict__ out) {
    int tid = threadIdx.x;          // 256 threads = 8 warps
    int img = tid >> 5, lane = tid & 31;
    float v0 = 0, v1 = 0, v2 = 0, v3 = 0;
    for (int b = lane; b < GRIDX; b += 32) {
        int base = (img * GRIDX + b) * 4;
        v0 += g_part[base + 0];
        v1 += g_part[base + 1];
        v2 += g_part[base + 2];
        v3 += g_part[base + 3];
    }
    #pragma unroll
    for (int o = 16; o > 0; o >>= 1) {
        v0 += __shfl_down_sync(0xFFFFFFFFu, v0, o);
        v1 += __shfl_down_sync(0xFFFFFFFFu, v1, o);
        v2 += __shfl_down_sync(0xFFFFFFFFu, v2, o);
        v3 += __shfl_down_sync(0xFFFFFFFFu, v3, o);
    }
    __shared__ float li[NIMG];
    if (lane == 0)
        li[img] = v0 / fmaxf(v2, 1.0f) + v1 / fmaxf(v3, 1.0f);   // ALPHA = 1
    __syncthreads();
    if (tid == 0) {
        float sum = 0.0f;
        for (int i = 0; i < NIMG; i++) sum += li[i];
        out[0] = sum / (float)NIMG;
    }
}

// ---------------------------------------------------------------------------
extern "C" void kernel_launch(void* const* d_in, const int* in_sizes, int n_in,
                              void* d_out, int out_size) {
    const float* inp    = (const float*)d_in[0];
    const float* tgt    = (const float*)d_in[1];
    const float* images = (const float*)d_in[2];
    const int*   anc    = (const int*)d_in[3];
    const int*   dst    = (const int*)d_in[4];
    float* out = (float*)d_out;

    k_init<<<1, 32>>>();
    k_sobel_max<<<dim3(H - 2, NIMG), 256>>>(images);
    k_bits<<<dim3(H, NIMG), 256>>>(images);
    k_scan_local<<<dim3(NBLK, NIMG), 1024>>>();
    k_scan_offsets<<<1, 256>>>();
    k_anchor<<<dim3(GRIDX, NIMG), 256>>>(inp, tgt, images, anc, dst);
    k_final<<<1, 256>>>(out);
}

// round 5
// speedup vs baseline: 1.9093x; 1.0257x over previous
#include <cuda_runtime.h>
#include <cuda_bf16.h>
#include <math.h>

// Problem constants
#define NIMG 8
#define H 768
#define W 1024
#define HW (H*W)              // 786432
#define S 30000
#define WORDS (HW/32)         // 24576
#define CHUNK_ROWS 16
#define NBLK (H/CHUNK_ROWS)   // 48 chunks per image, 512 words each
#define CHUNK_WORDS (CHUNK_ROWS*32)  // 512
#define GRIDX ((S+255)/256)   // 118
#define MASKV (-1e-8f)

// Scratch (device globals -- no allocation allowed)
__device__ unsigned g_bits[NIMG*WORDS];    // edge-mask bitmask, 32 px/word
__device__ int      g_prefix[NIMG*WORDS];  // LOCAL inclusive popcount prefix per 512-word chunk
__device__ int      g_bsum[NIMG*NBLK];     // per-chunk popcount totals
__device__ float    g_strip_max[NIMG*NBLK];// per-strip Sobel max (no atomics needed)
__device__ float    g_part[NIMG*GRIDX*4];  // per-block partials: eq, un, n_eq, n_un

// ---------------------------------------------------------------------------
// Sobel arithmetic: EXACT rounding sequence (no fma contraction), row-major.
// ---------------------------------------------------------------------------
__device__ __forceinline__ void sobel_gxgy(float a00, float a01, float a02,
                                           float a10, float a12,
                                           float a20, float a21, float a22,
                                           float& gx, float& gy) {
    float x = __fmul_rn(-1.0f, a00);
    x = __fadd_rn(x, a02);
    x = __fadd_rn(x, __fmul_rn(-2.0f, a10));
    x = __fadd_rn(x, __fmul_rn( 2.0f, a12));
    x = __fadd_rn(x, __fmul_rn(-1.0f, a20));
    x = __fadd_rn(x, a22);
    gx = x;
    float y = a00;
    y = __fadd_rn(y, __fmul_rn( 2.0f, a01));
    y = __fadd_rn(y, a02);
    y = __fadd_rn(y, __fmul_rn(-1.0f, a20));
    y = __fadd_rn(y, __fmul_rn(-2.0f, a21));
    y = __fadd_rn(y, __fmul_rn(-1.0f, a22));
    gy = y;
}

__device__ __forceinline__ float edge_mag(float gx, float gy) {
    float e2 = __fadd_rn(__fadd_rn(__fmul_rn(gx, gx), __fmul_rn(gy, gy)), 1e-6f);
    return sqrtf(e2);
}

// Load one row segment: 6-wide window for 4 px starting at col 4*tid.
// w[0]=col-1 .. w[5]=col+4; missing edge cols read 0 (consumed only by
// border pixels whose result is forced off anyway).
__device__ __forceinline__ void load_row(const float* __restrict__ row, int tid,
                                         float w[6]) {
    float4 m = *(const float4*)(row + tid * 4);
    w[1] = m.x; w[2] = m.y; w[3] = m.z; w[4] = m.w;
    w[0] = (tid > 0)   ? row[tid * 4 - 1] : 0.0f;
    w[5] = (tid < 255) ? row[tid * 4 + 4] : 0.0f;
}

__device__ __forceinline__ void rot_copy(float dst[6], const float src[6]) {
    #pragma unroll
    for (int i = 0; i < 6; i++) dst[i] = src[i];
}

// ---------------------------------------------------------------------------
// Pass 1: 16-row strip Sobel max with rolling 3-row register window.
// Writes per-strip max (unconditionally) -- no init kernel, no atomics.
__global__ void k_sobel_max(const float* __restrict__ images) {
    const int strip = blockIdx.x;            // 0..47
    const int img   = blockIdx.y;
    const int tid   = threadIdx.x;
    const float* g  = images + (size_t)img * 3 * HW;

    const int rs = strip * CHUNK_ROWS;
    const int rb = rs == 0 ? 1 : rs;                 // first interior row
    const int re = min(rs + CHUNK_ROWS, H - 1);      // exclusive end

    float w0[6], w1[6], w2[6];
    load_row(g + (rb - 1) * W, tid, w0);
    load_row(g + rb * W, tid, w1);

    float em = 0.0f;
    for (int r = rb; r < re; r++) {
        load_row(g + (r + 1) * W, tid, w2);
        #pragma unroll
        for (int i = 0; i < 4; i++) {
            float gx, gy;
            sobel_gxgy(w0[i], w0[i+1], w0[i+2],
                       w1[i],          w1[i+2],
                       w2[i], w2[i+1], w2[i+2], gx, gy);
            float e = edge_mag(gx, gy);
            if ((tid == 0 && i == 0) || (tid == 255 && i == 3)) e = 0.0f;
            em = fmaxf(em, e);
        }
        rot_copy(w0, w1);
        rot_copy(w1, w2);
    }

    // warp max -> smem -> warp0 -> one global store per block
    #pragma unroll
    for (int o = 16; o > 0; o >>= 1)
        em = fmaxf(em, __shfl_down_sync(0xFFFFFFFFu, em, o));
    __shared__ float wmax[8];
    if ((tid & 31) == 0) wmax[tid >> 5] = em;
    __syncthreads();
    if (tid == 0) {
        float m = wmax[0];
        #pragma unroll
        for (int i = 1; i < 8; i++) m = fmaxf(m, wmax[i]);
        g_strip_max[img * NBLK + strip] = m;
    }
}

// Pass 2 (fused): reduce strip maxima -> threshold -> bitmask words ->
// local prefix scan, one 16-row chunk (512 words) per block.
__global__ void k_bits_scan(const float* __restrict__ images) {
    const int chunk = blockIdx.x;            // 0..47
    const int img   = blockIdx.y;
    const int tid   = threadIdx.x;
    const int lane  = tid & 31, wid = tid >> 5;
    const float* g  = images + (size_t)img * 3 * HW;

    __shared__ unsigned words[CHUNK_WORDS];
    __shared__ int warr[8];
    __shared__ float thr_s;

    // image max over 48 strip maxima (order-independent, exact)
    if (tid < 32) {
        float m = g_strip_max[img * NBLK + tid];
        if (tid + 32 < NBLK) m = fmaxf(m, g_strip_max[img * NBLK + tid + 32]);
        #pragma unroll
        for (int o = 16; o > 0; o >>= 1)
            m = fmaxf(m, __shfl_down_sync(0xFFFFFFFFu, m, o));
        if (tid == 0) thr_s = __fmul_rn(m, 0.1f);
    }
    __syncthreads();
    const float thr = thr_s;

    const int rs = chunk * CHUNK_ROWS;
    const int rb = rs == 0 ? 1 : rs;
    const int re = min(rs + CHUNK_ROWS, H - 1);

    float w0[6], w1[6], w2[6];
    load_row(g + (rb - 1) * W, tid, w0);
    load_row(g + rb * W, tid, w1);

    for (int r = rb; r < re; r++) {
        load_row(g + (r + 1) * W, tid, w2);
        unsigned nib = 0;
        #pragma unroll
        for (int i = 0; i < 4; i++) {
            float gx, gy;
            sobel_gxgy(w0[i], w0[i+1], w0[i+2],
                       w1[i],          w1[i+2],
                       w2[i], w2[i+1], w2[i+2], gx, gy);
            bool on = edge_mag(gx, gy) >= thr;
            if ((tid == 0 && i == 0) || (tid == 255 && i == 3)) on = false;
            nib |= (unsigned)on << i;
        }
        // pack 8 threads' nibbles -> one 32-bit word (3 shuffles)
        unsigned v = nib;
        v |= __shfl_down_sync(0xFFFFFFFFu, v, 1) << 4;
        v |= __shfl_down_sync(0xFFFFFFFFu, v, 2) << 8;
        v |= __shfl_down_sync(0xFFFFFFFFu, v, 4) << 16;
        if ((lane & 7) == 0) words[(r - rs) * 32 + (tid >> 3)] = v;
        rot_copy(w0, w1);
        rot_copy(w1, w2);
    }
    // border rows (row 0 / row H-1) produce zero words
    if (chunk == 0 && tid < 32)        words[tid] = 0;
    if (chunk == NBLK - 1 && tid < 32) words[(CHUNK_ROWS - 1) * 32 + tid] = 0;
    __syncthreads();

    // scan 512 words: 2 words/thread
    const int gbase = img * WORDS + chunk * CHUNK_WORDS;
    unsigned b0 = words[2 * tid], b1 = words[2 * tid + 1];
    *(uint2*)(g_bits + gbase + 2 * tid) = make_uint2(b0, b1);
    int i0 = __popc(b0);
    int i1 = i0 + __popc(b1);
    int tot = i1;
    int v = tot;
    #pragma unroll
    for (int o = 1; o < 32; o <<= 1) {
        int t = __shfl_up_sync(0xFFFFFFFFu, v, o);
        if (lane >= o) v += t;
    }
    if (lane == 31) warr[wid] = v;
    int excl = v - tot;
    __syncthreads();
    if (tid < 8) {
        int x = warr[tid];
        #pragma unroll
        for (int o = 1; o < 8; o <<= 1) {
            int t = __shfl_up_sync(0x000000FFu, x, o);
            if (tid >= o) x += t;
        }
        warr[tid] = x;   // inclusive warp totals
    }
    __syncthreads();
    int off = (wid ? warr[wid - 1] : 0) + excl;
    *(int2*)(g_prefix + gbase + 2 * tid) = make_int2(off + i0, off + i1);
    if (tid == 255) g_bsum[img * NBLK + chunk] = off + i1;
}

// Pass 3: per-anchor sampling + ranking loss; chunk-offset scan in prologue.
__global__ void k_anchor(const float* __restrict__ inp,
                         const float* __restrict__ tgt,
                         const float* __restrict__ images,
                         const int* __restrict__ anchor_rand,
                         const int* __restrict__ dist_rand) {
    const int img = blockIdx.y;
    const int s   = blockIdx.x * 256 + threadIdx.x;

    __shared__ int boff_s[NBLK];
    __shared__ int cnt_s;
    if (threadIdx.x < 32) {
        const int base = img * NBLK;
        const int lane = threadIdx.x;
        int vlo = g_bsum[base + lane];
        int vhi = (lane + 32 < NBLK) ? g_bsum[base + lane + 32] : 0;
        int olo = vlo, ohi = vhi;
        #pragma unroll
        for (int o = 1; o < 32; o <<= 1) {
            int t = __shfl_up_sync(0xFFFFFFFFu, vlo, o);
            if (lane >= o) vlo += t;
        }
        int tlo = __shfl_sync(0xFFFFFFFFu, vlo, 31);
        #pragma unroll
        for (int o = 1; o < 32; o <<= 1) {
            int t = __shfl_up_sync(0xFFFFFFFFu, vhi, o);
            if (lane >= o) vhi += t;
        }
        vhi += tlo;
        boff_s[lane] = vlo - olo;
        if (lane + 32 < NBLK) boff_s[lane + 32] = vhi - ohi;
        if (lane + 32 == NBLK - 1) cnt_s = vhi;
    }
    __syncthreads();

    float eq = 0.0f, un = 0.0f, ne = 0.0f, nu = 0.0f;

    if (s < S) {
        const float UP = logf(1.03f);
        const float LO = logf(0.9708737864077669f);   // f32(1.0/1.03 in double)

        int k = anchor_rand[img * S + s] % cnt_s;

        // level 1: which 512-word chunk (largest b with boff<=k)
        int b = 0;
        #pragma unroll
        for (int i = 1; i < NBLK; i++) if (boff_s[i] <= k) b = i;
        int k2 = k - boff_s[b];

        // level 2: binary search local inclusive prefix (smallest w with P>k2)
        const int base = img * WORDS + b * CHUNK_WORDS;
        int lo = 0, hi = CHUNK_WORDS;
        while (lo < hi) {
            int mid = (lo + hi) >> 1;
            if (g_prefix[base + mid] > k2) hi = mid; else lo = mid + 1;
        }
        int prev = lo ? g_prefix[base + lo - 1] : 0;
        int j = k2 - prev;
        unsigned wbits = g_bits[base + lo];
        for (int t = 0; t < j; t++) wbits &= wbits - 1;   // drop j lowest set bits
        int sel = (b * CHUNK_WORDS + lo) * 32 + (__ffs(wbits) - 1);

        int ra = sel >> 10, ca = sel & 1023;              // W = 1024
        const float* g = images + (size_t)img * 3 * HW;
        const float* r0 = g + (ra - 1) * W + ca;
        const float* r1 = g + ra * W + ca;
        const float* r2 = g + (ra + 1) * W + ca;
        float gx, gy;
        sobel_gxgy(r0[-1], r0[0], r0[1], r1[-1], r1[1], r2[-1], r2[0], r2[1], gx, gy);
        float th = atan2f(gy, gx);
        float ct = cosf(th), st = sinf(th);

        int lin[4];
        #pragma unroll
        for (int jj = 0; jj < 4; jj++) {
            float d = (float)dist_rand[(img * 4 + jj) * S + s] + 2.0f;
            if (jj < 2) d = -d;                           // sign = [-1,-1,1,1]
            int cc = ca + (int)rintf(__fmul_rn(d, ct));   // half-to-even round
            int rr = ra + (int)rintf(__fmul_rn(d, st));
            cc = min(max(cc, 0), W - 1);
            rr = min(max(rr, 0), H - 1);
            lin[jj] = rr * W + cc;
        }

        const float* ip = inp + (size_t)img * HW;
        const float* tp = tgt + (size_t)img * HW;
        #pragma unroll
        for (int p = 0; p < 3; p++) {
            int a = lin[p], bq = lin[p + 1];
            float iA = ip[a], iB = ip[bq];
            float trA = tp[a], trB = tp[bq];
            float cm = (trA > MASKV && trB > MASKV) ? 1.0f : 0.0f;
            float lr = __fadd_rn(logf(fmaxf(trA, 1e-8f)), -logf(fmaxf(trB, 1e-8f)));
            float diff = iA - iB;
            bool meq = (lr < UP) && (lr > LO);
            if (meq) {
                float ad = fabsf(diff);
                float sl1 = (ad < 1.0f) ? 0.5f * diff * diff : ad - 0.5f;
                eq += sl1 * cm;
                ne += cm;
            } else {
                float lab = (lr >= UP) ? 1.0f : -1.0f;
                float x = -diff * lab;
                float sp = fmaxf(x, 0.0f) + log1pf(expf(-fabsf(x)));  // softplus
                un += sp * cm;
                nu += cm;
            }
        }
    }

    // warp shuffle tree + fixed-order cross-warp sum (deterministic)
    #pragma unroll
    for (int o = 16; o > 0; o >>= 1) {
        eq += __shfl_down_sync(0xFFFFFFFFu, eq, o);
        un += __shfl_down_sync(0xFFFFFFFFu, un, o);
        ne += __shfl_down_sync(0xFFFFFFFFu, ne, o);
        nu += __shfl_down_sync(0xFFFFFFFFu, nu, o);
    }
    __shared__ float s0[8], s1[8], s2[8], s3[8];
    int t = threadIdx.x;
    if ((t & 31) == 0) {
        int w = t >> 5;
        s0[w] = eq; s1[w] = un; s2[w] = ne; s3[w] = nu;
    }
    __syncthreads();
    if (t == 0) {
        float a0 = s0[0], a1 = s1[0], a2 = s2[0], a3 = s3[0];
        #pragma unroll
        for (int w = 1; w < 8; w++) {
            a0 += s0[w]; a1 += s1[w]; a2 += s2[w]; a3 += s3[w];
        }
        int base = (img * GRIDX + blockIdx.x) * 4;
        g_part[base + 0] = a0;
        g_part[base + 1] = a1;
        g_part[base + 2] = a2;
        g_part[base + 3] = a3;
    }
}

// Pass 4: final reduction. 1 warp per image (fixed-order strided + shuffle tree).
__global__ void k_final(float* __restrict__ out) {
    int tid = threadIdx.x;          // 256 threads = 8 warps
    int img = tid >> 5, lane = tid & 31;
    float v0 = 0, v1 = 0, v2 = 0, v3 = 0;
    for (int b = lane; b < GRIDX; b += 32) {
        int base = (img * GRIDX + b) * 4;
        v0 += g_part[base + 0];
        v1 += g_part[base + 1];
        v2 += g_part[base + 2];
        v3 += g_part[base + 3];
    }
    #pragma unroll
    for (int o = 16; o > 0; o >>= 1) {
        v0 += __shfl_down_sync(0xFFFFFFFFu, v0, o);
        v1 += __shfl_down_sync(0xFFFFFFFFu, v1, o);
        v2 += __shfl_down_sync(0xFFFFFFFFu, v2, o);
        v3 += __shfl_down_sync(0xFFFFFFFFu, v3, o);
    }
    __shared__ float li[NIMG];
    if (lane == 0)
        li[img] = v0 / fmaxf(v2, 1.0f) + v1 / fmaxf(v3, 1.0f);   // ALPHA = 1
    __syncthreads();
    if (tid == 0) {
        float sum = 0.0f;
        for (int i = 0; i < NIMG; i++) sum += li[i];
        out[0] = sum / (float)NIMG;
    }
}

// ---------------------------------------------------------------------------
extern "C" void kernel_launch(void* const* d_in, const int* in_sizes, int n_in,
                              void* d_out, int out_size) {
    const float* inp    = (const float*)d_in[0];
    const float* tgt    = (const float*)d_in[1];
    const float* images = (const float*)d_in[2];
    const int*   anc    = (const int*)d_in[3];
    const int*   dst    = (const int*)d_in[4];
    float* out = (float*)d_out;

    k_sobel_max<<<dim3(NBLK, NIMG), 256>>>(images);
    k_bits_scan<<<dim3(NBLK, NIMG), 256>>>(images);
    k_anchor<<<dim3(GRIDX, NIMG), 256>>>(inp, tgt, images, anc, dst);
    k_final<<<1, 256>>>(out);
}

// round 6
// speedup vs baseline: 2.1921x; 1.1481x over previous
#include <cuda_runtime.h>
#include <cuda_bf16.h>
#include <math.h>

// Problem constants
#define NIMG 8
#define H 768
#define W 1024
#define HW (H*W)              // 786432
#define S 30000
#define WORDS (HW/32)         // 24576
#define CHUNK_ROWS 16
#define NBLK (H/CHUNK_ROWS)   // 48 chunks per image, 512 words each
#define CHUNK_WORDS (CHUNK_ROWS*32)  // 512
#define GRIDX ((S+255)/256)   // 118
#define MASKV (-1e-8f)

// dynamic smem layout for k_edges: e[16*1024] floats, words[512], pad
#define SMEM_E_FLOATS (CHUNK_ROWS*W)                  // 16384
#define SMEM_EDGES_BYTES (SMEM_E_FLOATS*4 + CHUNK_WORDS*4 + 64)

// Scratch (device globals -- no allocation allowed)
__device__ unsigned g_bits[NIMG*WORDS];    // edge-mask bitmask, 32 px/word
__device__ int      g_prefix[NIMG*WORDS];  // LOCAL inclusive popcount prefix per 512-word chunk
__device__ int      g_bsum[NIMG*NBLK];     // per-chunk popcount totals
__device__ float    g_strip_max[NIMG*NBLK];// per-strip Sobel max
__device__ int      g_arrive[NIMG];        // inter-block barrier counters (reset by k_anchor)
__device__ int      g_done;                // k_anchor completion ticket (reset by last block)
__device__ float    g_part[NIMG*GRIDX*4];  // per-block partials: eq, un, n_eq, n_un

// ---------------------------------------------------------------------------
// Sobel arithmetic: EXACT rounding sequence (no fma contraction), row-major.
// ---------------------------------------------------------------------------
__device__ __forceinline__ void sobel_gxgy(float a00, float a01, float a02,
                                           float a10, float a12,
                                           float a20, float a21, float a22,
                                           float& gx, float& gy) {
    float x = __fmul_rn(-1.0f, a00);
    x = __fadd_rn(x, a02);
    x = __fadd_rn(x, __fmul_rn(-2.0f, a10));
    x = __fadd_rn(x, __fmul_rn( 2.0f, a12));
    x = __fadd_rn(x, __fmul_rn(-1.0f, a20));
    x = __fadd_rn(x, a22);
    gx = x;
    float y = a00;
    y = __fadd_rn(y, __fmul_rn( 2.0f, a01));
    y = __fadd_rn(y, a02);
    y = __fadd_rn(y, __fmul_rn(-1.0f, a20));
    y = __fadd_rn(y, __fmul_rn(-2.0f, a21));
    y = __fadd_rn(y, __fmul_rn(-1.0f, a22));
    gy = y;
}

__device__ __forceinline__ float edge_mag(float gx, float gy) {
    float e2 = __fadd_rn(__fadd_rn(__fmul_rn(gx, gx), __fmul_rn(gy, gy)), 1e-6f);
    return sqrtf(e2);
}

// Load one row segment: 6-wide window for 4 px starting at col 4*tid.
__device__ __forceinline__ void load_row(const float* __restrict__ row, int tid,
                                         float w[6]) {
    float4 m = *(const float4*)(row + tid * 4);
    w[1] = m.x; w[2] = m.y; w[3] = m.z; w[4] = m.w;
    w[0] = (tid > 0)   ? row[tid * 4 - 1] : 0.0f;
    w[5] = (tid < 255) ? row[tid * 4 + 4] : 0.0f;
}

__device__ __forceinline__ void rot_copy(float dst[6], const float src[6]) {
    #pragma unroll
    for (int i = 0; i < 6; i++) dst[i] = src[i];
}

// ---------------------------------------------------------------------------
// Fused pass: Sobel strip -> smem e-values + strip max -> inter-block barrier
// (all 384 blocks co-resident: 67.6KB smem = 3 blocks/SM, 444 slots >= 384)
// -> image max -> threshold from smem -> bitmask words -> local prefix scan.
__global__ void k_edges(const float* __restrict__ images) {
    extern __shared__ float dyn[];
    float*    e_s   = dyn;                                    // [16][1024]
    unsigned* words = (unsigned*)(dyn + SMEM_E_FLOATS);       // [512]
    __shared__ int   warr[8];
    __shared__ float thr_s;

    const int chunk = blockIdx.x;            // 0..47
    const int img   = blockIdx.y;
    const int tid   = threadIdx.x;
    const int lane  = tid & 31, wid = tid >> 5;
    const float* g  = images + (size_t)img * 3 * HW;

    const int rs = chunk * CHUNK_ROWS;
    const int rb = rs == 0 ? 1 : rs;
    const int re = min(rs + CHUNK_ROWS, H - 1);

    // ---- Phase A: compute edge magnitudes for this strip into smem ----
    float w0[6], w1[6], w2[6];
    load_row(g + (rb - 1) * W, tid, w0);
    load_row(g + rb * W, tid, w1);

    float em = 0.0f;
    for (int r = rb; r < re; r++) {
        load_row(g + (r + 1) * W, tid, w2);
        float4 ev;
        float e4[4];
        #pragma unroll
        for (int i = 0; i < 4; i++) {
            float gx, gy;
            sobel_gxgy(w0[i], w0[i+1], w0[i+2],
                       w1[i],          w1[i+2],
                       w2[i], w2[i+1], w2[i+2], gx, gy);
            float e = edge_mag(gx, gy);
            if ((tid == 0 && i == 0) || (tid == 255 && i == 3)) e = 0.0f;
            e4[i] = e;
            em = fmaxf(em, e);
        }
        ev.x = e4[0]; ev.y = e4[1]; ev.z = e4[2]; ev.w = e4[3];
        *(float4*)(e_s + (r - rs) * W + tid * 4) = ev;
        rot_copy(w0, w1);
        rot_copy(w1, w2);
    }
    // border rows (image row 0 / H-1) -> e = 0
    if (chunk == 0) {
        float4 z = make_float4(0.f, 0.f, 0.f, 0.f);
        *(float4*)(e_s + tid * 4) = z;
    }
    if (chunk == NBLK - 1) {
        float4 z = make_float4(0.f, 0.f, 0.f, 0.f);
        *(float4*)(e_s + (CHUNK_ROWS - 1) * W + tid * 4) = z;
    }

    // ---- publish strip max, inter-block barrier on this image ----
    #pragma unroll
    for (int o = 16; o > 0; o >>= 1)
        em = fmaxf(em, __shfl_down_sync(0xFFFFFFFFu, em, o));
    __shared__ float wmax[8];
    if (lane == 0) wmax[wid] = em;
    __syncthreads();
    if (tid == 0) {
        float m = wmax[0];
        #pragma unroll
        for (int i = 1; i < 8; i++) m = fmaxf(m, wmax[i]);
        g_strip_max[img * NBLK + chunk] = m;
        __threadfence();
        atomicAdd(&g_arrive[img], 1);
        // spin until all 48 strips of this image have arrived
        while (*(volatile int*)&g_arrive[img] < NBLK) __nanosleep(32);
    }
    __syncthreads();

    // ---- image max over 48 strip maxima -> threshold ----
    if (tid < 32) {
        float m = g_strip_max[img * NBLK + tid];
        if (tid + 32 < NBLK) m = fmaxf(m, g_strip_max[img * NBLK + tid + 32]);
        #pragma unroll
        for (int o = 16; o > 0; o >>= 1)
            m = fmaxf(m, __shfl_down_sync(0xFFFFFFFFu, m, o));
        if (tid == 0) thr_s = __fmul_rn(m, 0.1f);
    }
    __syncthreads();
    const float thr = thr_s;

    // ---- Phase B: threshold smem e-values -> bitmask words ----
    #pragma unroll 1
    for (int lr = 0; lr < CHUNK_ROWS; lr++) {
        float4 ev = *(const float4*)(e_s + lr * W + tid * 4);
        unsigned nib = (unsigned)(ev.x >= thr)
                     | ((unsigned)(ev.y >= thr) << 1)
                     | ((unsigned)(ev.z >= thr) << 2)
                     | ((unsigned)(ev.w >= thr) << 3);
        unsigned v = nib;
        v |= __shfl_down_sync(0xFFFFFFFFu, v, 1) << 4;
        v |= __shfl_down_sync(0xFFFFFFFFu, v, 2) << 8;
        v |= __shfl_down_sync(0xFFFFFFFFu, v, 4) << 16;
        if ((lane & 7) == 0) words[lr * 32 + (tid >> 3)] = v;
    }
    __syncthreads();

    // ---- local prefix scan of 512 words (2/thread) ----
    const int gbase = img * WORDS + chunk * CHUNK_WORDS;
    unsigned b0 = words[2 * tid], b1 = words[2 * tid + 1];
    *(uint2*)(g_bits + gbase + 2 * tid) = make_uint2(b0, b1);
    int i0 = __popc(b0);
    int i1 = i0 + __popc(b1);
    int tot = i1;
    int v = tot;
    #pragma unroll
    for (int o = 1; o < 32; o <<= 1) {
        int t = __shfl_up_sync(0xFFFFFFFFu, v, o);
        if (lane >= o) v += t;
    }
    if (lane == 31) warr[wid] = v;
    int excl = v - tot;
    __syncthreads();
    if (tid < 8) {
        int x = warr[tid];
        #pragma unroll
        for (int o = 1; o < 8; o <<= 1) {
            int t = __shfl_up_sync(0x000000FFu, x, o);
            if (tid >= o) x += t;
        }
        warr[tid] = x;
    }
    __syncthreads();
    int off = (wid ? warr[wid - 1] : 0) + excl;
    *(int2*)(g_prefix + gbase + 2 * tid) = make_int2(off + i0, off + i1);
    if (tid == 255) g_bsum[img * NBLK + chunk] = off + i1;
}

// ---------------------------------------------------------------------------
// Pass 2: per-anchor sampling + ranking loss; chunk-offset scan in prologue;
// last finishing block performs the fixed-order final reduction.
__global__ void k_anchor(const float* __restrict__ inp,
                         const float* __restrict__ tgt,
                         const float* __restrict__ images,
                         const int* __restrict__ anchor_rand,
                         const int* __restrict__ dist_rand,
                         float* __restrict__ out) {
    const int img = blockIdx.y;
    const int s   = blockIdx.x * 256 + threadIdx.x;

    // reset k_edges barrier counters for the next graph replay
    if (blockIdx.x == 0 && threadIdx.x == 0) g_arrive[img] = 0;

    __shared__ int boff_s[NBLK];
    __shared__ int cnt_s;
    if (threadIdx.x < 32) {
        const int base = img * NBLK;
        const int lane = threadIdx.x;
        int vlo = g_bsum[base + lane];
        int vhi = (lane + 32 < NBLK) ? g_bsum[base + lane + 32] : 0;
        int olo = vlo, ohi = vhi;
        #pragma unroll
        for (int o = 1; o < 32; o <<= 1) {
            int t = __shfl_up_sync(0xFFFFFFFFu, vlo, o);
            if (lane >= o) vlo += t;
        }
        int tlo = __shfl_sync(0xFFFFFFFFu, vlo, 31);
        #pragma unroll
        for (int o = 1; o < 32; o <<= 1) {
            int t = __shfl_up_sync(0xFFFFFFFFu, vhi, o);
            if (lane >= o) vhi += t;
        }
        vhi += tlo;
        boff_s[lane] = vlo - olo;
        if (lane + 32 < NBLK) boff_s[lane + 32] = vhi - ohi;
        if (lane + 32 == NBLK - 1) cnt_s = vhi;
    }
    __syncthreads();

    float eq = 0.0f, un = 0.0f, ne = 0.0f, nu = 0.0f;

    if (s < S) {
        const float UP = logf(1.03f);
        const float LO = logf(0.9708737864077669f);   // f32(1.0/1.03 in double)

        int k = anchor_rand[img * S + s] % cnt_s;

        // level 1: which 512-word chunk (largest b with boff<=k)
        int b = 0;
        #pragma unroll
        for (int i = 1; i < NBLK; i++) if (boff_s[i] <= k) b = i;
        int k2 = k - boff_s[b];

        // level 2: binary search local inclusive prefix (smallest w with P>k2)
        const int base = img * WORDS + b * CHUNK_WORDS;
        int lo = 0, hi = CHUNK_WORDS;
        while (lo < hi) {
            int mid = (lo + hi) >> 1;
            if (g_prefix[base + mid] > k2) hi = mid; else lo = mid + 1;
        }
        int prev = lo ? g_prefix[base + lo - 1] : 0;
        int j = k2 - prev;
        unsigned wbits = g_bits[base + lo];
        for (int t = 0; t < j; t++) wbits &= wbits - 1;   // drop j lowest set bits
        int sel = (b * CHUNK_WORDS + lo) * 32 + (__ffs(wbits) - 1);

        int ra = sel >> 10, ca = sel & 1023;              // W = 1024
        const float* g = images + (size_t)img * 3 * HW;
        const float* r0 = g + (ra - 1) * W + ca;
        const float* r1 = g + ra * W + ca;
        const float* r2 = g + (ra + 1) * W + ca;
        float gx, gy;
        sobel_gxgy(r0[-1], r0[0], r0[1], r1[-1], r1[1], r2[-1], r2[0], r2[1], gx, gy);
        float th = atan2f(gy, gx);
        float ct = cosf(th), st = sinf(th);

        int lin[4];
        #pragma unroll
        for (int jj = 0; jj < 4; jj++) {
            float d = (float)dist_rand[(img * 4 + jj) * S + s] + 2.0f;
            if (jj < 2) d = -d;                           // sign = [-1,-1,1,1]
            int cc = ca + (int)rintf(__fmul_rn(d, ct));   // half-to-even round
            int rr = ra + (int)rintf(__fmul_rn(d, st));
            cc = min(max(cc, 0), W - 1);
            rr = min(max(rr, 0), H - 1);
            lin[jj] = rr * W + cc;
        }

        const float* ip = inp + (size_t)img * HW;
        const float* tp = tgt + (size_t)img * HW;
        #pragma unroll
        for (int p = 0; p < 3; p++) {
            int a = lin[p], bq = lin[p + 1];
            float iA = ip[a], iB = ip[bq];
            float trA = tp[a], trB = tp[bq];
            float cm = (trA > MASKV && trB > MASKV) ? 1.0f : 0.0f;
            float lr = __fadd_rn(logf(fmaxf(trA, 1e-8f)), -logf(fmaxf(trB, 1e-8f)));
            float diff = iA - iB;
            bool meq = (lr < UP) && (lr > LO);
            if (meq) {
                float ad = fabsf(diff);
                float sl1 = (ad < 1.0f) ? 0.5f * diff * diff : ad - 0.5f;
                eq += sl1 * cm;
                ne += cm;
            } else {
                float lab = (lr >= UP) ? 1.0f : -1.0f;
                float x = -diff * lab;
                float sp = fmaxf(x, 0.0f) + log1pf(expf(-fabsf(x)));  // softplus
                un += sp * cm;
                nu += cm;
            }
        }
    }

    // warp shuffle tree + fixed-order cross-warp sum (deterministic)
    #pragma unroll
    for (int o = 16; o > 0; o >>= 1) {
        eq += __shfl_down_sync(0xFFFFFFFFu, eq, o);
        un += __shfl_down_sync(0xFFFFFFFFu, un, o);
        ne += __shfl_down_sync(0xFFFFFFFFu, ne, o);
        nu += __shfl_down_sync(0xFFFFFFFFu, nu, o);
    }
    __shared__ float s0[8], s1[8], s2[8], s3[8];
    __shared__ int last_s;
    int t = threadIdx.x;
    if ((t & 31) == 0) {
        int w = t >> 5;
        s0[w] = eq; s1[w] = un; s2[w] = ne; s3[w] = nu;
    }
    __syncthreads();
    if (t == 0) {
        float a0 = s0[0], a1 = s1[0], a2 = s2[0], a3 = s3[0];
        #pragma unroll
        for (int w = 1; w < 8; w++) {
            a0 += s0[w]; a1 += s1[w]; a2 += s2[w]; a3 += s3[w];
        }
        int base = (img * GRIDX + blockIdx.x) * 4;
        g_part[base + 0] = a0;
        g_part[base + 1] = a1;
        g_part[base + 2] = a2;
        g_part[base + 3] = a3;
        __threadfence();
        int ticket = atomicAdd(&g_done, 1);
        last_s = (ticket == NIMG * GRIDX - 1) ? 1 : 0;
    }
    __syncthreads();

    // last finishing block: fixed-order final reduction (deterministic)
    if (last_s) {
        __threadfence();
        int fimg = t >> 5, lane = t & 31;
        float v0 = 0, v1 = 0, v2 = 0, v3 = 0;
        for (int b = lane; b < GRIDX; b += 32) {
            int base = (fimg * GRIDX + b) * 4;
            v0 += g_part[base + 0];
            v1 += g_part[base + 1];
            v2 += g_part[base + 2];
            v3 += g_part[base + 3];
        }
        #pragma unroll
        for (int o = 16; o > 0; o >>= 1) {
            v0 += __shfl_down_sync(0xFFFFFFFFu, v0, o);
            v1 += __shfl_down_sync(0xFFFFFFFFu, v1, o);
            v2 += __shfl_down_sync(0xFFFFFFFFu, v2, o);
            v3 += __shfl_down_sync(0xFFFFFFFFu, v3, o);
        }
        __shared__ float li[NIMG];
        if (lane == 0)
            li[fimg] = v0 / fmaxf(v2, 1.0f) + v1 / fmaxf(v3, 1.0f);  // ALPHA=1
        __syncthreads();
        if (t == 0) {
            float sum = 0.0f;
            for (int i = 0; i < NIMG; i++) sum += li[i];
            out[0] = sum / (float)NIMG;
            g_done = 0;                      // reset for next graph replay
        }
    }
}

// ---------------------------------------------------------------------------
extern "C" void kernel_launch(void* const* d_in, const int* in_sizes, int n_in,
                              void* d_out, int out_size) {
    const float* inp    = (const float*)d_in[0];
    const float* tgt    = (const float*)d_in[1];
    const float* images = (const float*)d_in[2];
    const int*   anc    = (const int*)d_in[3];
    const int*   dst    = (const int*)d_in[4];
    float* out = (float*)d_out;

    static bool attr_set = false;
    if (!attr_set) {
        cudaFuncSetAttribute(k_edges, cudaFuncAttributeMaxDynamicSharedMemorySize,
                             SMEM_EDGES_BYTES);
        attr_set = true;
    }

    k_edges<<<dim3(NBLK, NIMG), 256, SMEM_EDGES_BYTES>>>(images);
    k_anchor<<<dim3(GRIDX, NIMG), 256>>>(inp, tgt, images, anc, dst, out);
}